// round 6
// baseline (speedup 1.0000x reference)
#include <cuda_runtime.h>

// VolumeRenderer: fused NeRF-style compositing.
// depth [R,128] f32 (sorted, in [2,6]), density [R,128] f32 (in [0,1)),
// feature [R,128,3] f32 -> out [R,4] f32 (r,g,b,depth)
//
// R6: persistent warps + software-pipelined double buffering. Each warp
// grid-strides over rays; the NEXT ray's 5 LDG.128 are issued before the
// CURRENT ray's scan/exp/reduce, so DRAM demand is continuous (no per-block
// burst/drain, no wave transitions). 1 ray per warp-iteration, lane owns 4
// consecutive samples. Exclusive scan base via shfl_up(inclusive,1) to avoid
// fp32 cancellation against the 1e10 FAR_DELTA tau at lane 31.

#define FULL 0xffffffffu

struct RayData {
    float4 dep, den, f0, f1, f2;
};

__device__ __forceinline__ void load_ray(int ray, int lane,
                                         const float4* __restrict__ depth,
                                         const float4* __restrict__ density,
                                         const float4* __restrict__ feature,
                                         RayData& r)
{
    const size_t row32 = (size_t)ray * 32;   // 128 floats = 32 float4
    const size_t row96 = (size_t)ray * 96;   // 384 floats = 96 float4
    r.dep = __ldcs(depth   + row32 + lane);
    r.den = __ldcs(density + row32 + lane);
    const float4* frow = feature + row96 + lane * 3;
    r.f0 = __ldcs(frow + 0);  // {p0.r, p0.g, p0.b, p1.r}
    r.f1 = __ldcs(frow + 1);  // {p1.g, p1.b, p2.r, p2.g}
    r.f2 = __ldcs(frow + 2);  // {p2.b, p3.r, p3.g, p3.b}
}

__device__ __forceinline__ void compute_ray(int ray, int lane, const RayData& R,
                                            float* __restrict__ out)
{
    // deltas: depth[j+1]-depth[j]; last sample of the ray gets 1e10
    float nxt = __shfl_down_sync(FULL, R.dep.x, 1);
    float t0 = R.den.x * (R.dep.y - R.dep.x);
    float t1 = R.den.y * (R.dep.z - R.dep.y);
    float t2 = R.den.z * (R.dep.w - R.dep.z);
    float t3 = R.den.w * ((lane == 31) ? 1e10f : (nxt - R.dep.w));

    // per-lane inclusive prefix of tau
    float s0 = t0;
    float s1 = s0 + t1;
    float s2 = s1 + t2;
    float s3 = s2 + t3;   // lane 31: contains the 1e10 sentinel

    // warp inclusive scan of per-lane totals (Kogge-Stone)
    float v = s3;
    #pragma unroll
    for (int off = 1; off < 32; off <<= 1) {
        float n = __shfl_up_sync(FULL, v, off);
        if (lane >= off) v += n;
    }
    // exclusive base = previous lane's inclusive value (no subtraction ->
    // no cancellation against the sentinel term at lane 31)
    float base = __shfl_up_sync(FULL, v, 1);
    if (lane == 0) base = 0.0f;

    // w_j = exp(-excl_j) - exp(-incl_j); 5 exps per lane
    float ep = __expf(-base);
    float e0 = __expf(-(base + s0));
    float e1 = __expf(-(base + s1));
    float e2 = __expf(-(base + s2));
    float e3 = __expf(-(base + s3));   // lane31: underflows to 0
    float w0 = ep - e0, w1 = e0 - e1, w2 = e1 - e2, w3 = e2 - e3;

    // weighted accumulation (feature components per float4 packing)
    float r = w0*R.f0.x + w1*R.f0.w + w2*R.f1.z + w3*R.f2.y;
    float g = w0*R.f0.y + w1*R.f1.x + w2*R.f1.w + w3*R.f2.z;
    float b = w0*R.f0.z + w1*R.f1.y + w2*R.f2.x + w3*R.f2.w;
    float d = w0*R.dep.x + w1*R.dep.y + w2*R.dep.z + w3*R.dep.w;

    // 4-component reduction in 11 shuffles
    #pragma unroll
    for (int off = 1; off <= 2; off <<= 1) {
        r += __shfl_xor_sync(FULL, r, off);
        g += __shfl_xor_sync(FULL, g, off);
        b += __shfl_xor_sync(FULL, b, off);
        d += __shfl_xor_sync(FULL, d, off);
    }
    int c = lane & 3;
    float val = (c == 0) ? r : (c == 1) ? g : (c == 2) ? b : d;
    #pragma unroll
    for (int off = 4; off < 32; off <<= 1)
        val += __shfl_xor_sync(FULL, val, off);

    if (lane < 4) out[(size_t)ray * 4 + lane] = val;
}

__global__ __launch_bounds__(256, 4)
void vr_kernel(const float4* __restrict__ inA,   // depth OR density
               const float4* __restrict__ inB,   // the other one
               const float4* __restrict__ feature,
               float*  __restrict__ out,         // [R,4] flat
               int n_rays, int stride)           // stride = total warps in grid
{
    // Disambiguate depth vs density by value range (depth >= 2, density < 1).
    const float probe = ((const float*)inA)[0];
    const float4* __restrict__ depth   = (probe >= 2.0f) ? inA : inB;
    const float4* __restrict__ density = (probe >= 2.0f) ? inB : inA;

    const int lane = threadIdx.x & 31;
    int ray = (blockIdx.x * blockDim.x + threadIdx.x) >> 5;
    if (ray >= n_rays) return;

    RayData A;
    load_ray(ray, lane, depth, density, feature, A);

    int nray = ray + stride;
    while (nray < n_rays) {
        RayData B;
        load_ray(nray, lane, depth, density, feature, B);  // in flight during compute
        compute_ray(ray, lane, A, out);
        A = B;
        ray = nray;
        nray += stride;
    }
    compute_ray(ray, lane, A, out);
}

extern "C" void kernel_launch(void* const* d_in, const int* in_sizes, int n_in,
                              void* d_out, int out_size)
{
    // feature = the (unique) largest input; remaining two disambiguated
    // in-kernel by value range.
    int fi = 2;
    for (int i = 0; i < 3; ++i)
        if (in_sizes[i] > in_sizes[(i + 1) % 3] && in_sizes[i] > in_sizes[(i + 2) % 3]) fi = i;
    int a = (fi == 0) ? 1 : 0;
    int b = (fi == 2) ? 1 : 2;
    if (b == fi || b == a) b = 3 - a - fi;

    const float4* inA     = (const float4*)d_in[a];
    const float4* inB     = (const float4*)d_in[b];
    const float4* feature = (const float4*)d_in[fi];
    float* out = (float*)d_out;

    int n_rays = in_sizes[a] / 128;

    // Persistent grid: 4 blocks/SM (reg-pressure cap), host-side query runs
    // only at capture time (free at graph replay).
    int sm_count = 148;
    cudaDeviceGetAttribute(&sm_count, cudaDevAttrMultiProcessorCount, 0);
    int blocks = sm_count * 4;
    int warps_per_block = 256 / 32;
    int total_warps = blocks * warps_per_block;
    if (total_warps > n_rays) {   // degenerate small inputs
        blocks = (n_rays + warps_per_block - 1) / warps_per_block;
        total_warps = blocks * warps_per_block;
    }
    vr_kernel<<<blocks, 256>>>(inA, inB, feature, out, n_rays, total_warps);
}